// round 13
// baseline (speedup 1.0000x reference)
#include <cuda_runtime.h>
#include <cuda_fp16.h>
#include <math.h>
#include <stdint.h>

#define BATCH 8
#define SEQ   2048
#define DMODEL 1024
#define DKV   128
#define DFF   4096
#define MS    (BATCH*SEQ)

// ---------------- scratch (static device globals) ----------------------------
__device__ float    g_xnF[(size_t)MS*DMODEL];
__device__ float    g_yF [(size_t)MS*DMODEL];

__device__ uint32_t g_xnH[(size_t)MS*DMODEL/2];
__device__ uint32_t g_hH [(size_t)MS*DMODEL/2];
__device__ uint32_t g_qH [(size_t)MS*DKV/2];
__device__ uint32_t g_ktH[(size_t)BATCH*DKV*SEQ/2];
__device__ uint32_t g_vH [(size_t)MS*DKV/2];
__device__ uint32_t g_atH[(size_t)MS*DKV/2];
__device__ uint32_t g_acH[(size_t)MS*DFF/2];

// weights in mma-B-fragment order: [npair][kt][lane][4 u32]
__device__ uint32_t g_wqkvF[(size_t)DMODEL*384/2];
__device__ float    g_bqkv[384];
__device__ uint32_t g_woF[(size_t)DKV*DMODEL/2];
__device__ uint32_t g_w1F[(size_t)DMODEL*DFF/2];
__device__ uint32_t g_w2F[(size_t)DFF*DMODEL/2];

// ---------------- helpers ----------------------------------------------------
__device__ __forceinline__ uint32_t smem_u32(const void* p) {
    uint32_t a;
    asm("{ .reg .u64 t; cvta.to.shared.u64 t, %1; cvt.u32.u64 %0, t; }" : "=r"(a) : "l"(p));
    return a;
}
__device__ __forceinline__ void cpasync16(uint32_t dst, const void* src) {
    asm volatile("cp.async.cg.shared.global [%0], [%1], 16;" :: "r"(dst), "l"(src));
}
#define CP_COMMIT() asm volatile("cp.async.commit_group;" ::: "memory")
#define CP_WAIT1()  asm volatile("cp.async.wait_group 1;" ::: "memory")
#define CP_WAIT2()  asm volatile("cp.async.wait_group 2;" ::: "memory")

__device__ __forceinline__ void ldm_x4(uint32_t r[4], uint32_t addr) {
    asm volatile("ldmatrix.sync.aligned.m8n8.x4.shared.b16 {%0,%1,%2,%3}, [%4];"
                 : "=r"(r[0]), "=r"(r[1]), "=r"(r[2]), "=r"(r[3]) : "r"(addr));
}
__device__ __forceinline__ void ldm_x4_t(uint32_t r[4], uint32_t addr) {
    asm volatile("ldmatrix.sync.aligned.m8n8.x4.trans.shared.b16 {%0,%1,%2,%3}, [%4];"
                 : "=r"(r[0]), "=r"(r[1]), "=r"(r[2]), "=r"(r[3]) : "r"(addr));
}
__device__ __forceinline__ void mma16816(float c[4], const uint32_t a[4], const uint32_t b[2]) {
    asm volatile("mma.sync.aligned.m16n8k16.row.col.f32.f16.f16.f32 "
                 "{%0,%1,%2,%3},{%4,%5,%6,%7},{%8,%9},{%0,%1,%2,%3};"
                 : "+f"(c[0]), "+f"(c[1]), "+f"(c[2]), "+f"(c[3])
                 : "r"(a[0]), "r"(a[1]), "r"(a[2]), "r"(a[3]), "r"(b[0]), "r"(b[1]));
}
__device__ __forceinline__ uint32_t packh(__half a, __half b) {
    return (uint32_t)__half_as_ushort(a) | ((uint32_t)__half_as_ushort(b) << 16);
}
__device__ __forceinline__ uint32_t pack2(float a, float b) {
    return packh(__float2half_rn(a), __float2half_rn(b));
}
__device__ __forceinline__ float gelu1(float v) {
    return 0.5f * v * (1.0f + erff(v * 0.70710678118654752f));
}

// ---------------- one-shot weight conversion -> fragment order ---------------
struct WJobs {
    const float* wq; const float* wk; const float* wv;
    const float* wo; const float* w1; const float* w2;
    uint32_t* dqkv; uint32_t* dwo; uint32_t* dw1; uint32_t* dw2;
    const float* bq; const float* bk; const float* bv;
    float* bqkv;
    int blkStart[5];
};

__global__ __launch_bounds__(256) void wconv_all(WJobs jb)
{
    const int blk = blockIdx.x, tid = threadIdx.x;
    if (blk >= jb.blkStart[4]) {
        if (tid < 128) {
            jb.bqkv[tid]       = jb.bq[tid];
            jb.bqkv[128 + tid] = jb.bk[tid];
            jb.bqkv[256 + tid] = jb.bv[tid];
        }
        return;
    }
    int seg = 0;
    #pragma unroll
    for (int s = 1; s < 4; s++) if (blk >= jb.blkStart[s]) seg = s;
    int u = (blk - jb.blkStart[seg]) * 256 + tid;

    int N, K;
    const float* W = nullptr;
    uint32_t* D;
    if (seg == 0)      { N = 384;  K = DMODEL; D = jb.dqkv; }
    else if (seg == 1) { N = DMODEL; K = DKV;  W = jb.wo; D = jb.dwo; }
    else if (seg == 2) { N = DFF;  K = DMODEL; W = jb.w1; D = jb.dw1; }
    else               { N = DMODEL; K = DFF;  W = jb.w2; D = jb.dw2; }

    int perN = K * 8;
    int npair = u / perN;
    int rem = u - npair * perN;
    int kt = rem >> 7, w = rem & 127;
    int lane = w >> 2, r4 = w & 3;
    int n = npair * 16 + ((r4 >> 1) << 3) + (lane >> 2);
    int k = (kt << 4) + ((r4 & 1) << 3) + ((lane & 3) << 1);

    float a, b;
    if (seg == 0) {
        const float* S;
        int nn = n;
        if (n < 128)      { S = jb.wq; }
        else if (n < 256) { S = jb.wk; nn = n - 128; }
        else              { S = jb.wv; nn = n - 256; }
        a = S[(size_t)k * 128 + nn];
        b = S[(size_t)(k + 1) * 128 + nn];
    } else {
        a = W[(size_t)k * N + n];
        b = W[(size_t)(k + 1) * N + n];
    }
    D[u] = pack2(a, b);
}

// ---------------- LayerNorm ---------------------------------------------------
template<bool WF32>
__global__ __launch_bounds__(256) void ln_frag(const float* __restrict__ x,
                                               const float* __restrict__ g,
                                               const float* __restrict__ b,
                                               float* __restrict__ oF,
                                               uint32_t* __restrict__ H)
{
    const int row = blockIdx.x;
    const int tid = threadIdx.x;
    const float* xr = x + (size_t)row * DMODEL;
    float4 v = *(const float4*)(xr + tid * 4);

    float s  = v.x + v.y + v.z + v.w;
    float s2 = v.x*v.x + v.y*v.y + v.z*v.z + v.w*v.w;
    #pragma unroll
    for (int off = 16; off; off >>= 1) {
        s  += __shfl_xor_sync(0xffffffffu, s,  off);
        s2 += __shfl_xor_sync(0xffffffffu, s2, off);
    }
    __shared__ float ss[8], ss2[8], stats[2];
    const int wid = tid >> 5, lane = tid & 31;
    if (lane == 0) { ss[wid] = s; ss2[wid] = s2; }
    __syncthreads();
    if (wid == 0) {
        s  = (lane < 8) ? ss[lane]  : 0.f;
        s2 = (lane < 8) ? ss2[lane] : 0.f;
        #pragma unroll
        for (int off = 4; off; off >>= 1) {
            s  += __shfl_xor_sync(0xffffffffu, s,  off);
            s2 += __shfl_xor_sync(0xffffffffu, s2, off);
        }
        if (lane == 0) {
            float mean = s * (1.0f / DMODEL);
            float var  = s2 * (1.0f / DMODEL) - mean * mean;
            stats[0] = mean;
            stats[1] = rsqrtf(var + 1e-5f);
        }
    }
    __syncthreads();
    const float mean = stats[0], rstd = stats[1];
    float4 gg = *(const float4*)(g + tid * 4);
    float4 bb = *(const float4*)(b + tid * 4);
    float4 o;
    o.x = (v.x - mean) * rstd * gg.x + bb.x;
    o.y = (v.y - mean) * rstd * gg.y + bb.y;
    o.z = (v.z - mean) * rstd * gg.z + bb.z;
    o.w = (v.w - mean) * rstd * gg.w + bb.w;
    if (WF32) *(float4*)(oF + (size_t)row * DMODEL + tid * 4) = o;
    size_t base = (size_t)row * (DMODEL / 2) + tid * 2;
    H[base]     = pack2(o.x, o.y);
    H[base + 1] = pack2(o.z, o.w);
}

#define EM_F32 0
#define EM_QKV 3
#define EM_HF  4

// ================= flash attention (unchanged) ===============================
__global__ __launch_bounds__(128, 2)
void flash_attn(const uint32_t* __restrict__ qH,
                const uint32_t* __restrict__ ktH, const uint32_t* __restrict__ vH,
                uint32_t* __restrict__ atH, float scl2)
{
    extern __shared__ char smc[];
    const uint32_t sb = smem_u32(smc);
    const int tid = threadIdx.x, wid = tid >> 5, lane = tid & 31;
    const int q = lane >> 3, l7 = lane & 7;
    const int b = blockIdx.y, qt = blockIdx.x;

    auto load_q = [&] {
        #pragma unroll
        for (int t = 0; t < 8; t++) {
            int id = tid + t * 128;
            int m = id >> 4, ch = id & 15;
            cpasync16(sb + m * 256 + ((ch ^ (m & 15)) << 4),
                      qH + ((size_t)(b * 2048 + qt * 64 + m)) * 64 + ch * 4);
        }
    };
    auto load_kv = [&](int st, int j) {
        const uint32_t stb = sb + 16384 + st * 32768;
        #pragma unroll
        for (int t = 0; t < 8; t++) {
            int id = tid + t * 128;
            int d = id >> 3, ch = id & 7;
            cpasync16(stb + d * 128 + ((ch ^ (d & 7)) << 4),
                      ktH + ((size_t)b * 128 + d) * 1024 + j * 32 + ch * 4);
        }
        #pragma unroll
        for (int t = 0; t < 8; t++) {
            int id = tid + t * 128;
            int s = id >> 4, ch = id & 15;
            cpasync16(stb + 16384 + s * 256 + ((ch ^ (s & 15)) << 4),
                      vH + ((size_t)(b * 2048 + j * 64 + s)) * 64 + ch * 4);
        }
    };

    load_q(); load_kv(0, 0); CP_COMMIT();
    load_kv(1, 1); CP_COMMIT();

    float oa[16][4];
    #pragma unroll
    for (int jd = 0; jd < 16; jd++)
        #pragma unroll
        for (int r = 0; r < 4; r++) oa[jd][r] = 0.f;
    float m0 = -1e30f, m1 = -1e30f, l0 = 0.f, l1 = 0.f;

    for (int j = 0; j < 32; ++j) {
        CP_WAIT1();
        __syncthreads();
        const uint32_t stb = sb + 16384 + (j & 1) * 32768;

        float sa[8][4];
        #pragma unroll
        for (int jn = 0; jn < 8; jn++)
            #pragma unroll
            for (int r = 0; r < 4; r++) sa[jn][r] = 0.f;

        #pragma unroll
        for (int ks = 0; ks < 8; ks++) {
            uint32_t aH4[4];
            int m = wid * 16 + ((q & 1) << 3) + l7;
            int ch = 2 * ks + (q >> 1);
            ldm_x4(aH4, sb + m * 256 + ((ch ^ (m & 15)) << 4));
            #pragma unroll
            for (int g = 0; g < 4; g++) {
                uint32_t b4[4];
                int k = ks * 16 + ((q & 1) << 3) + l7;
                int bch = g * 2 + (q >> 1);
                ldm_x4_t(b4, stb + k * 128 + ((bch ^ (k & 7)) << 4));
                mma16816(sa[2 * g],     aH4, &b4[0]);
                mma16816(sa[2 * g + 1], aH4, &b4[2]);
            }
        }

        float mx0 = -1e30f, mx1 = -1e30f;
        #pragma unroll
        for (int jn = 0; jn < 8; jn++) {
            sa[jn][0] *= scl2; sa[jn][1] *= scl2;
            sa[jn][2] *= scl2; sa[jn][3] *= scl2;
            mx0 = fmaxf(mx0, fmaxf(sa[jn][0], sa[jn][1]));
            mx1 = fmaxf(mx1, fmaxf(sa[jn][2], sa[jn][3]));
        }
        mx0 = fmaxf(mx0, __shfl_xor_sync(0xffffffffu, mx0, 1));
        mx0 = fmaxf(mx0, __shfl_xor_sync(0xffffffffu, mx0, 2));
        mx1 = fmaxf(mx1, __shfl_xor_sync(0xffffffffu, mx1, 1));
        mx1 = fmaxf(mx1, __shfl_xor_sync(0xffffffffu, mx1, 2));

        float mn0 = fmaxf(m0, mx0), mn1 = fmaxf(m1, mx1);
        float c0 = exp2f(m0 - mn0), c1 = exp2f(m1 - mn1);
        m0 = mn0; m1 = mn1;

        float rs0 = 0.f, rs1 = 0.f;
        #pragma unroll
        for (int jn = 0; jn < 8; jn++) {
            sa[jn][0] = exp2f(sa[jn][0] - mn0);
            sa[jn][1] = exp2f(sa[jn][1] - mn0);
            sa[jn][2] = exp2f(sa[jn][2] - mn1);
            sa[jn][3] = exp2f(sa[jn][3] - mn1);
            rs0 += sa[jn][0] + sa[jn][1];
            rs1 += sa[jn][2] + sa[jn][3];
        }
        rs0 += __shfl_xor_sync(0xffffffffu, rs0, 1);
        rs0 += __shfl_xor_sync(0xffffffffu, rs0, 2);
        rs1 += __shfl_xor_sync(0xffffffffu, rs1, 1);
        rs1 += __shfl_xor_sync(0xffffffffu, rs1, 2);
        l0 = l0 * c0 + rs0;
        l1 = l1 * c1 + rs1;
        #pragma unroll
        for (int jd = 0; jd < 16; jd++) {
            oa[jd][0] *= c0; oa[jd][1] *= c0;
            oa[jd][2] *= c1; oa[jd][3] *= c1;
        }

        #pragma unroll
        for (int t = 0; t < 4; t++) {
            uint32_t pa[4];
            pa[0] = pack2(sa[2 * t][0],     sa[2 * t][1]);
            pa[1] = pack2(sa[2 * t][2],     sa[2 * t][3]);
            pa[2] = pack2(sa[2 * t + 1][0], sa[2 * t + 1][1]);
            pa[3] = pack2(sa[2 * t + 1][2], sa[2 * t + 1][3]);
            int k = t * 16 + ((q & 1) << 3) + l7;
            #pragma unroll
            for (int g = 0; g < 8; g++) {
                uint32_t b4[4];
                int bch = g * 2 + (q >> 1);
                ldm_x4_t(b4, stb + 16384 + k * 256 + ((bch ^ (k & 15)) << 4));
                mma16816(oa[2 * g],     pa, &b4[0]);
                mma16816(oa[2 * g + 1], pa, &b4[2]);
            }
        }

        __syncthreads();
        if (j + 2 < 32) load_kv(j & 1, j + 2);
        CP_COMMIT();
    }

    const float i0 = 1.0f / l0, i1 = 1.0f / l1;
    const size_t row0 = (size_t)(b * 2048 + qt * 64 + wid * 16 + (lane >> 2));
    const int qc = lane & 3;
    #pragma unroll
    for (int jd = 0; jd < 16; jd++) {
        atH[row0 * 64 + 4 * jd + qc]       = pack2(oa[jd][0] * i0, oa[jd][1] * i0);
        atH[(row0 + 8) * 64 + 4 * jd + qc] = pack2(oa[jd][2] * i1, oa[jd][3] * i1);
    }
}

// ======== 1-pass GEMM: A smem (4 stages), B fragment-LDG w/ prefetch =========
// 128 thr, warp 64x64, BM=BN=128, 2 CTAs/SM.
template<int EMIT, int EPI>
__global__ __launch_bounds__(128, 2)
void hg1pW(const uint32_t* __restrict__ Ah, const uint32_t* __restrict__ Bf,
           const float* __restrict__ bias, const float* __restrict__ res,
           float* __restrict__ outF, uint32_t* __restrict__ outH,
           uint32_t* __restrict__ outH2, uint32_t* __restrict__ outH3,
           int Ka, int Nb, int nc, float alpha)
{
    extern __shared__ char smc[];
    const uint32_t sb = smem_u32(smc);
    const int tid = threadIdx.x, wid = tid >> 5, lane = tid & 31;
    const int wm = wid >> 1, wn = wid & 1;
    const int bx = blockIdx.x, by = blockIdx.y;

    const uint32_t Ka2 = (uint32_t)Ka >> 1;
    const int KT = Ka >> 4;

    auto load_stage = [&](int st, int c) {
        const uint32_t stb = sb + st * 16384;
        #pragma unroll
        for (int t = 0; t < 8; t++) {
            int id = tid + t * 128;
            int m = id >> 3, ch = id & 7;
            size_t go = (size_t)(by * 128 + m) * Ka2 + (size_t)c * 32 + ch * 4;
            cpasync16(stb + m * 128 + ((ch ^ (m & 7)) << 4), Ah + go);
        }
    };

    // per-warp B fragment base: 4 consecutive npairs, stride KT*32 uint4 each
    const int npair0 = bx * 8 + wn * 4;
    const uint4* Bw = (const uint4*)Bf + (size_t)npair0 * KT * 32 + lane;
    const size_t gstep = (size_t)KT * 32;

    float acc[4][8][4];
    #pragma unroll
    for (int i = 0; i < 4; i++)
        #pragma unroll
        for (int j = 0; j < 8; j++)
            #pragma unroll
            for (int r = 0; r < 4; r++) acc[i][j][r] = 0.f;

    load_stage(0, 0); CP_COMMIT();
    if (nc > 1) load_stage(1, 1);
    CP_COMMIT();
    if (nc > 2) load_stage(2, 2);
    CP_COMMIT();

    const int q = lane >> 3, l7 = lane & 7;

    // prefetch B for kt=0 (issued while cp.async stages land)
    uint4 bv[4];
    #pragma unroll
    for (int g = 0; g < 4; g++) bv[g] = __ldg(Bw + g * gstep);

    for (int c = 0; c < nc; ++c) {
        CP_WAIT2();
        __syncthreads();
        if (c + 3 < nc) load_stage((c + 3) & 3, c + 3);
        CP_COMMIT();

        const uint32_t stb = sb + (c & 3) * 16384;
        #pragma unroll
        for (int ks = 0; ks < 4; ks++) {
            const int kt = c * 4 + ks;
            const int ktn = (kt + 1 < KT) ? (kt + 1) : kt;
            // prefetch next kt's B fragments FIRST (covered by this ks's mma)
            uint4 bn[4];
            #pragma unroll
            for (int g = 0; g < 4; g++)
                bn[g] = __ldg(Bw + g * gstep + (size_t)ktn * 32);

            uint32_t aH[4][4];
            #pragma unroll
            for (int i = 0; i < 4; i++) {
                int m = wm * 64 + i * 16 + ((q & 1) << 3) + l7;
                int ch = 2 * ks + (q >> 1);
                ldm_x4(aH[i], stb + m * 128 + ((ch ^ (m & 7)) << 4));
            }
            #pragma unroll
            for (int g = 0; g < 4; g++) {
                uint32_t bH4[4] = {bv[g].x, bv[g].y, bv[g].z, bv[g].w};
                #pragma unroll
                for (int i = 0; i < 4; i++) {
                    mma16816(acc[i][g * 2 + 0], aH[i], &bH4[0]);
                    mma16816(acc[i][g * 2 + 1], aH[i], &bH4[2]);
                }
            }
            #pragma unroll
            for (int g = 0; g < 4; g++) bv[g] = bn[g];
        }
    }

    __syncthreads();
    float* Cs = (float*)smc;
    #pragma unroll
    for (int i = 0; i < 4; i++)
        #pragma unroll
        for (int j = 0; j < 8; j++) {
            int r0 = wm * 64 + i * 16 + (lane >> 2);
            int c0 = wn * 64 + j * 8 + 2 * (lane & 3);
            *(float2*)(Cs + r0 * 132 + c0)       = make_float2(acc[i][j][0], acc[i][j][1]);
            *(float2*)(Cs + (r0 + 8) * 132 + c0) = make_float2(acc[i][j][2], acc[i][j][3]);
        }
    __syncthreads();

    if (EMIT == EM_F32) {
        #pragma unroll
        for (int i = 0; i < 32; i++) {
            int u = tid + 128 * i;
            int row = u >> 5, c4 = (u & 31) * 4;
            float4 v = *(float4*)(Cs + row * 132 + c4);
            v.x *= alpha; v.y *= alpha; v.z *= alpha; v.w *= alpha;
            int gc = bx * 128 + c4;
            size_t gm = (size_t)by * 128 + row;
            if (EPI & 1) {
                float4 bb = *(const float4*)(bias + gc);
                v.x += bb.x; v.y += bb.y; v.z += bb.z; v.w += bb.w;
            }
            if (EPI & 2) { v.x = gelu1(v.x); v.y = gelu1(v.y); v.z = gelu1(v.z); v.w = gelu1(v.w); }
            if (EPI & 4) {
                float4 rr = *(const float4*)(res + gm * Nb + gc);
                v.x += rr.x; v.y += rr.y; v.z += rr.z; v.w += rr.w;
            }
            *(float4*)(outF + gm * Nb + gc) = v;
        }
    } else if (EMIT == EM_HF) {
        #pragma unroll
        for (int i = 0; i < 64; i++) {
            int u = tid + 128 * i;
            int row = u >> 6, np = u & 63;
            float v0 = Cs[row * 132 + 2 * np]     * alpha;
            float v1 = Cs[row * 132 + 2 * np + 1] * alpha;
            int gc = bx * 128 + 2 * np;
            if (EPI & 1) { v0 += __ldg(bias + gc); v1 += __ldg(bias + gc + 1); }
            if (EPI & 2) { v0 = gelu1(v0); v1 = gelu1(v1); }
            size_t gm = (size_t)by * 128 + row;
            outH[gm * (Nb >> 1) + (size_t)bx * 64 + np] = pack2(v0, v1);
        }
    } else { // EM_QKV: bx=0 q, bx=1 kT transposed, bx=2 v
        if (bx == 1) {
            const int b = by >> 4;
            const int s0p = (by & 15) * 64;
            #pragma unroll
            for (int i = 0; i < 64; i++) {
                int u = tid + 128 * i;
                int d = u >> 6, sp = u & 63;
                float bb = __ldg(bias + 128 + d);
                float v0 = Cs[(2 * sp) * 132 + d]     + bb;
                float v1 = Cs[(2 * sp + 1) * 132 + d] + bb;
                outH2[(size_t)b * (DKV * SEQ / 2) + (size_t)d * (SEQ / 2) + s0p + sp] = pack2(v0, v1);
            }
        } else {
            uint32_t* oh = (bx == 0) ? outH : outH3;
            const int boff = (bx == 0) ? 0 : 256;
            #pragma unroll
            for (int i = 0; i < 64; i++) {
                int u = tid + 128 * i;
                int row = u >> 6, np = u & 63;
                float v0 = Cs[row * 132 + 2 * np]     + __ldg(bias + boff + 2 * np);
                float v1 = Cs[row * 132 + 2 * np + 1] + __ldg(bias + boff + 2 * np + 1);
                oh[((size_t)by * 128 + row) * 64 + np] = pack2(v0, v1);
            }
        }
    }
}

// ---------------- launch sequence -------------------------------------------
extern "C" void kernel_launch(void* const* d_in, const int* in_sizes, int n_in,
                              void* d_out, int out_size)
{
    const float* x     = (const float*)d_in[0];
    const float* ln1_g = (const float*)d_in[1];
    const float* ln1_b = (const float*)d_in[2];
    const float* Wq    = (const float*)d_in[3];
    const float* bq    = (const float*)d_in[4];
    const float* Wk    = (const float*)d_in[5];
    const float* bk    = (const float*)d_in[6];
    const float* Wv    = (const float*)d_in[7];
    const float* bv    = (const float*)d_in[8];
    const float* Wo    = (const float*)d_in[9];
    const float* bo    = (const float*)d_in[10];
    const float* ln2_g = (const float*)d_in[11];
    const float* ln2_b = (const float*)d_in[12];
    const float* W1    = (const float*)d_in[13];
    const float* b1    = (const float*)d_in[14];
    const float* W2    = (const float*)d_in[15];
    const float* b2    = (const float*)d_in[16];
    float* out = (float*)d_out;

    float *xnF, *yF, *bqkv;
    uint32_t *xnH,*hH,*qH,*ktH,*vH,*atH,*acH;
    uint32_t *wqkvF,*woF,*w1F,*w2F;
    cudaGetSymbolAddress((void**)&xnF, g_xnF);
    cudaGetSymbolAddress((void**)&yF,  g_yF);  cudaGetSymbolAddress((void**)&bqkv, g_bqkv);
    cudaGetSymbolAddress((void**)&xnH, g_xnH);
    cudaGetSymbolAddress((void**)&hH,  g_hH);
    cudaGetSymbolAddress((void**)&qH,  g_qH);
    cudaGetSymbolAddress((void**)&ktH, g_ktH);
    cudaGetSymbolAddress((void**)&vH,  g_vH);
    cudaGetSymbolAddress((void**)&atH, g_atH);
    cudaGetSymbolAddress((void**)&acH, g_acH);
    cudaGetSymbolAddress((void**)&wqkvF, g_wqkvF);
    cudaGetSymbolAddress((void**)&woF, g_woF);
    cudaGetSymbolAddress((void**)&w1F, g_w1F);
    cudaGetSymbolAddress((void**)&w2F, g_w2F);

    const int SM_1P = 132 * 128 * 4;        // 67584 B (>= 4x16KB stages)
    const int SM_FL = 16384 + 2 * 32768;    // 80 KB
    cudaFuncSetAttribute(flash_attn,        cudaFuncAttributeMaxDynamicSharedMemorySize, SM_FL);
    cudaFuncSetAttribute(hg1pW<EM_QKV,1>,   cudaFuncAttributeMaxDynamicSharedMemorySize, SM_1P);
    cudaFuncSetAttribute(hg1pW<EM_F32,5>,   cudaFuncAttributeMaxDynamicSharedMemorySize, SM_1P);
    cudaFuncSetAttribute(hg1pW<EM_HF, 3>,   cudaFuncAttributeMaxDynamicSharedMemorySize, SM_1P);

    const float scl2 = 0.08838834764831845f * 1.4426950408889634f; // scale*log2(e)

    // ---- weight conversions -> fragment order (one launch) ----
    {
        WJobs jb;
        jb.wq = Wq; jb.wk = Wk; jb.wv = Wv;
        jb.wo = Wo; jb.w1 = W1; jb.w2 = W2;
        jb.dqkv = wqkvF; jb.dwo = woF; jb.dw1 = w1F; jb.dw2 = w2F;
        jb.bq = bq; jb.bk = bk; jb.bv = bv; jb.bqkv = bqkv;
        int counts[4] = { DMODEL*384/2, DKV*DMODEL/2, DMODEL*DFF/2, DFF*DMODEL/2 };
        int acc_ = 0;
        for (int s = 0; s < 4; s++) { jb.blkStart[s] = acc_; acc_ += (counts[s] + 255) / 256; }
        jb.blkStart[4] = acc_;
        wconv_all<<<acc_ + 1, 256>>>(jb);
    }

    // 2) ln1 -> xn (f32 + single fp16 pairs)
    ln_frag<true><<<MS, 256>>>(x, ln1_g, ln1_b, xnF, xnH);

    // 3) fused QKV (16384 x 384 x 1024): bx=0 q, 1 kT, 2 v
    hg1pW<EM_QKV, 1><<<dim3(3,128,1), 128, SM_1P>>>(xnH, wqkvF, bqkv, nullptr,
        nullptr, qH, ktH, vH, DMODEL, 384, 16, 1.f);

    // 4) flash attention -> att single fp16
    flash_attn<<<dim3(SEQ/64, BATCH), 128, SM_FL>>>(qH, ktH, vH, atH, scl2);

    // 5) y = xn + att@Wo + bo (16384x1024x128)
    hg1pW<EM_F32, 5><<<dim3(8,128,1), 128, SM_1P>>>(atH, woF, bo, xnF,
        yF, nullptr, nullptr, nullptr, DKV, DMODEL, 2, 1.f);

    // 6) ln2 -> h single pairs
    ln_frag<false><<<MS, 256>>>(yF, ln2_g, ln2_b, nullptr, hH);

    // 7) act = gelu(h@W1 + b1) (16384x4096x1024)
    hg1pW<EM_HF, 3><<<dim3(32,128,1), 128, SM_1P>>>(hH, w1F, b1, nullptr,
        nullptr, acH, nullptr, nullptr, DMODEL, DFF, 16, 1.f);

    // 8) out = y + act@W2 + b2 (16384x1024x4096)
    hg1pW<EM_F32, 5><<<dim3(8,128,1), 128, SM_1P>>>(acH, w2F, b2, yF,
        out, nullptr, nullptr, nullptr, DFF, DMODEL, 64, 1.f);
}

// round 14
// speedup vs baseline: 1.5607x; 1.5607x over previous
#include <cuda_runtime.h>
#include <cuda_fp16.h>
#include <math.h>
#include <stdint.h>

#define BATCH 8
#define SEQ   2048
#define DMODEL 1024
#define DKV   128
#define DFF   4096
#define MS    (BATCH*SEQ)

// ---------------- scratch (static device globals) ----------------------------
__device__ float    g_xnF[(size_t)MS*DMODEL];
__device__ float    g_yF [(size_t)MS*DMODEL];

__device__ uint32_t g_xnH[(size_t)MS*DMODEL/2];
__device__ uint32_t g_hH [(size_t)MS*DMODEL/2];
__device__ uint32_t g_qH [(size_t)MS*DKV/2];
__device__ uint32_t g_ktH[(size_t)BATCH*DKV*SEQ/2];
__device__ uint32_t g_vH [(size_t)MS*DKV/2];
__device__ uint32_t g_atH[(size_t)MS*DKV/2];
__device__ uint32_t g_acH[(size_t)MS*DFF/2];

__device__ uint32_t g_wqkvH[(size_t)DMODEL*384/2];
__device__ float    g_bqkv[384];
__device__ uint32_t g_woH[(size_t)DKV*DMODEL/2];
__device__ uint32_t g_w1H[(size_t)DMODEL*DFF/2];
__device__ uint32_t g_w2H[(size_t)DFF*DMODEL/2];

// ---------------- helpers ----------------------------------------------------
__device__ __forceinline__ uint32_t smem_u32(const void* p) {
    uint32_t a;
    asm("{ .reg .u64 t; cvta.to.shared.u64 t, %1; cvt.u32.u64 %0, t; }" : "=r"(a) : "l"(p));
    return a;
}
__device__ __forceinline__ void cpasync16(uint32_t dst, const void* src) {
    asm volatile("cp.async.cg.shared.global [%0], [%1], 16;" :: "r"(dst), "l"(src));
}
#define CP_COMMIT() asm volatile("cp.async.commit_group;" ::: "memory")
#define CP_WAIT1()  asm volatile("cp.async.wait_group 1;" ::: "memory")

__device__ __forceinline__ void ldm_x4(uint32_t r[4], uint32_t addr) {
    asm volatile("ldmatrix.sync.aligned.m8n8.x4.shared.b16 {%0,%1,%2,%3}, [%4];"
                 : "=r"(r[0]), "=r"(r[1]), "=r"(r[2]), "=r"(r[3]) : "r"(addr));
}
__device__ __forceinline__ void ldm_x4_t(uint32_t r[4], uint32_t addr) {
    asm volatile("ldmatrix.sync.aligned.m8n8.x4.trans.shared.b16 {%0,%1,%2,%3}, [%4];"
                 : "=r"(r[0]), "=r"(r[1]), "=r"(r[2]), "=r"(r[3]) : "r"(addr));
}
__device__ __forceinline__ void mma16816(float c[4], const uint32_t a[4], const uint32_t b[2]) {
    asm volatile("mma.sync.aligned.m16n8k16.row.col.f32.f16.f16.f32 "
                 "{%0,%1,%2,%3},{%4,%5,%6,%7},{%8,%9},{%0,%1,%2,%3};"
                 : "+f"(c[0]), "+f"(c[1]), "+f"(c[2]), "+f"(c[3])
                 : "r"(a[0]), "r"(a[1]), "r"(a[2]), "r"(a[3]), "r"(b[0]), "r"(b[1]));
}
__device__ __forceinline__ uint32_t packh(__half a, __half b) {
    return (uint32_t)__half_as_ushort(a) | ((uint32_t)__half_as_ushort(b) << 16);
}
__device__ __forceinline__ uint32_t pack2(float a, float b) {
    return packh(__float2half_rn(a), __float2half_rn(b));
}
__device__ __forceinline__ float gelu1(float v) {
    return 0.5f * v * (1.0f + erff(v * 0.70710678118654752f));
}

// ---------------- one-shot weight conversion ---------------------------------
struct WJobs {
    const float* src[6];
    uint32_t* H[6];
    int np[6];
    int srcP[6];
    int dstP[6];
    int coff[6];
    int blkStart[7];
    const float* bq; const float* bk; const float* bv;
    float* bqkv;
};

__global__ __launch_bounds__(256) void wconv_all(WJobs jb)
{
    const int blk = blockIdx.x, tid = threadIdx.x;
    if (blk >= jb.blkStart[6]) {
        if (tid < 128) {
            jb.bqkv[tid]       = jb.bq[tid];
            jb.bqkv[128 + tid] = jb.bk[tid];
            jb.bqkv[256 + tid] = jb.bv[tid];
        }
        return;
    }
    int seg = 0;
    #pragma unroll
    for (int s = 1; s < 6; s++) if (blk >= jb.blkStart[s]) seg = s;
    int u = (blk - jb.blkStart[seg]) * 256 + tid;
    if (u >= jb.np[seg]) return;
    int k = u / jb.srcP[seg], p = u - k * jb.srcP[seg];
    float2 v = *(const float2*)(jb.src[seg] + ((size_t)u) * 2);
    jb.H[seg][(size_t)k * jb.dstP[seg] + jb.coff[seg] + p] = pack2(v.x, v.y);
}

// ---------------- LayerNorm ---------------------------------------------------
template<bool WF32>
__global__ __launch_bounds__(256) void ln_frag(const float* __restrict__ x,
                                               const float* __restrict__ g,
                                               const float* __restrict__ b,
                                               float* __restrict__ oF,
                                               uint32_t* __restrict__ H)
{
    const int row = blockIdx.x;
    const int tid = threadIdx.x;
    const float* xr = x + (size_t)row * DMODEL;
    float4 v = *(const float4*)(xr + tid * 4);

    float s  = v.x + v.y + v.z + v.w;
    float s2 = v.x*v.x + v.y*v.y + v.z*v.z + v.w*v.w;
    #pragma unroll
    for (int off = 16; off; off >>= 1) {
        s  += __shfl_xor_sync(0xffffffffu, s,  off);
        s2 += __shfl_xor_sync(0xffffffffu, s2, off);
    }
    __shared__ float ss[8], ss2[8], stats[2];
    const int wid = tid >> 5, lane = tid & 31;
    if (lane == 0) { ss[wid] = s; ss2[wid] = s2; }
    __syncthreads();
    if (wid == 0) {
        s  = (lane < 8) ? ss[lane]  : 0.f;
        s2 = (lane < 8) ? ss2[lane] : 0.f;
        #pragma unroll
        for (int off = 4; off; off >>= 1) {
            s  += __shfl_xor_sync(0xffffffffu, s,  off);
            s2 += __shfl_xor_sync(0xffffffffu, s2, off);
        }
        if (lane == 0) {
            float mean = s * (1.0f / DMODEL);
            float var  = s2 * (1.0f / DMODEL) - mean * mean;
            stats[0] = mean;
            stats[1] = rsqrtf(var + 1e-5f);
        }
    }
    __syncthreads();
    const float mean = stats[0], rstd = stats[1];
    float4 gg = *(const float4*)(g + tid * 4);
    float4 bb = *(const float4*)(b + tid * 4);
    float4 o;
    o.x = (v.x - mean) * rstd * gg.x + bb.x;
    o.y = (v.y - mean) * rstd * gg.y + bb.y;
    o.z = (v.z - mean) * rstd * gg.z + bb.z;
    o.w = (v.w - mean) * rstd * gg.w + bb.w;
    if (WF32) *(float4*)(oF + (size_t)row * DMODEL + tid * 4) = o;
    size_t base = (size_t)row * (DMODEL / 2) + tid * 2;
    H[base]     = pack2(o.x, o.y);
    H[base + 1] = pack2(o.z, o.w);
}

#define EM_F32 0
#define EM_QKV 3
#define EM_HF  4

// ================= flash attention: 64-row Q tiles, 64-col KV tiles ==========
// 128 threads, 4 warps x 16 q rows. Q 16KB; KV double-buffered 2x32KB. 2 CTAs/SM.
__global__ __launch_bounds__(128, 2)
void flash_attn(const uint32_t* __restrict__ qH,
                const uint32_t* __restrict__ ktH, const uint32_t* __restrict__ vH,
                uint32_t* __restrict__ atH, float scl2)
{
    extern __shared__ char smc[];
    const uint32_t sb = smem_u32(smc);
    const int tid = threadIdx.x, wid = tid >> 5, lane = tid & 31;
    const int q = lane >> 3, l7 = lane & 7;
    const int b = blockIdx.y, qt = blockIdx.x;

    auto load_q = [&] {
        #pragma unroll
        for (int t = 0; t < 8; t++) {
            int id = tid + t * 128;
            int m = id >> 4, ch = id & 15;
            cpasync16(sb + m * 256 + ((ch ^ (m & 15)) << 4),
                      qH + ((size_t)(b * 2048 + qt * 64 + m)) * 64 + ch * 4);
        }
    };
    auto load_kv = [&](int st, int j) {
        const uint32_t stb = sb + 16384 + st * 32768;
        #pragma unroll
        for (int t = 0; t < 8; t++) {          // K: 128 d-rows x 64 s (128B rows)
            int id = tid + t * 128;
            int d = id >> 3, ch = id & 7;
            cpasync16(stb + d * 128 + ((ch ^ (d & 7)) << 4),
                      ktH + ((size_t)b * 128 + d) * 1024 + j * 32 + ch * 4);
        }
        #pragma unroll
        for (int t = 0; t < 8; t++) {          // V: 64 s-rows x 128 d (256B rows)
            int id = tid + t * 128;
            int s = id >> 4, ch = id & 15;
            cpasync16(stb + 16384 + s * 256 + ((ch ^ (s & 15)) << 4),
                      vH + ((size_t)(b * 2048 + j * 64 + s)) * 64 + ch * 4);
        }
    };

    load_q(); load_kv(0, 0); CP_COMMIT();
    load_kv(1, 1); CP_COMMIT();

    float oa[16][4];
    #pragma unroll
    for (int jd = 0; jd < 16; jd++)
        #pragma unroll
        for (int r = 0; r < 4; r++) oa[jd][r] = 0.f;
    float m0 = -1e30f, m1 = -1e30f, l0 = 0.f, l1 = 0.f;

    for (int j = 0; j < 32; ++j) {
        CP_WAIT1();
        __syncthreads();
        const uint32_t stb = sb + 16384 + (j & 1) * 32768;

        // ---- S = q @ kT (1-pass), 16q x 64s per warp ----
        float sa[8][4];
        #pragma unroll
        for (int jn = 0; jn < 8; jn++)
            #pragma unroll
            for (int r = 0; r < 4; r++) sa[jn][r] = 0.f;

        #pragma unroll
        for (int ks = 0; ks < 8; ks++) {
            uint32_t aH4[4];
            int m = wid * 16 + ((q & 1) << 3) + l7;
            int ch = 2 * ks + (q >> 1);
            ldm_x4(aH4, sb + m * 256 + ((ch ^ (m & 15)) << 4));
            #pragma unroll
            for (int g = 0; g < 4; g++) {
                uint32_t b4[4];
                int k = ks * 16 + ((q & 1) << 3) + l7;
                int bch = g * 2 + (q >> 1);
                ldm_x4_t(b4, stb + k * 128 + ((bch ^ (k & 7)) << 4));
                mma16816(sa[2 * g],     aH4, &b4[0]);
                mma16816(sa[2 * g + 1], aH4, &b4[2]);
            }
        }

        // ---- online softmax (base-2 domain) ----
        float mx0 = -1e30f, mx1 = -1e30f;
        #pragma unroll
        for (int jn = 0; jn < 8; jn++) {
            sa[jn][0] *= scl2; sa[jn][1] *= scl2;
            sa[jn][2] *= scl2; sa[jn][3] *= scl2;
            mx0 = fmaxf(mx0, fmaxf(sa[jn][0], sa[jn][1]));
            mx1 = fmaxf(mx1, fmaxf(sa[jn][2], sa[jn][3]));
        }
        mx0 = fmaxf(mx0, __shfl_xor_sync(0xffffffffu, mx0, 1));
        mx0 = fmaxf(mx0, __shfl_xor_sync(0xffffffffu, mx0, 2));
        mx1 = fmaxf(mx1, __shfl_xor_sync(0xffffffffu, mx1, 1));
        mx1 = fmaxf(mx1, __shfl_xor_sync(0xffffffffu, mx1, 2));

        float mn0 = fmaxf(m0, mx0), mn1 = fmaxf(m1, mx1);
        float c0 = exp2f(m0 - mn0), c1 = exp2f(m1 - mn1);
        m0 = mn0; m1 = mn1;

        float rs0 = 0.f, rs1 = 0.f;
        #pragma unroll
        for (int jn = 0; jn < 8; jn++) {
            sa[jn][0] = exp2f(sa[jn][0] - mn0);
            sa[jn][1] = exp2f(sa[jn][1] - mn0);
            sa[jn][2] = exp2f(sa[jn][2] - mn1);
            sa[jn][3] = exp2f(sa[jn][3] - mn1);
            rs0 += sa[jn][0] + sa[jn][1];
            rs1 += sa[jn][2] + sa[jn][3];
        }
        rs0 += __shfl_xor_sync(0xffffffffu, rs0, 1);
        rs0 += __shfl_xor_sync(0xffffffffu, rs0, 2);
        rs1 += __shfl_xor_sync(0xffffffffu, rs1, 1);
        rs1 += __shfl_xor_sync(0xffffffffu, rs1, 2);
        l0 = l0 * c0 + rs0;
        l1 = l1 * c1 + rs1;
        #pragma unroll
        for (int jd = 0; jd < 16; jd++) {
            oa[jd][0] *= c0; oa[jd][1] *= c0;
            oa[jd][2] *= c1; oa[jd][3] *= c1;
        }

        // ---- PV (1-pass fp16 P), contraction over 64 s ----
        #pragma unroll
        for (int t = 0; t < 4; t++) {
            uint32_t pa[4];
            pa[0] = pack2(sa[2 * t][0],     sa[2 * t][1]);
            pa[1] = pack2(sa[2 * t][2],     sa[2 * t][3]);
            pa[2] = pack2(sa[2 * t + 1][0], sa[2 * t + 1][1]);
            pa[3] = pack2(sa[2 * t + 1][2], sa[2 * t + 1][3]);
            int k = t * 16 + ((q & 1) << 3) + l7;
            #pragma unroll
            for (int g = 0; g < 8; g++) {
                uint32_t b4[4];
                int bch = g * 2 + (q >> 1);
                ldm_x4_t(b4, stb + 16384 + k * 256 + ((bch ^ (k & 15)) << 4));
                mma16816(oa[2 * g],     pa, &b4[0]);
                mma16816(oa[2 * g + 1], pa, &b4[2]);
            }
        }

        __syncthreads();
        if (j + 2 < 32) load_kv(j & 1, j + 2);
        CP_COMMIT();
    }

    // ---- finalize + emit att single fp16 pairs ----
    const float i0 = 1.0f / l0, i1 = 1.0f / l1;
    const size_t row0 = (size_t)(b * 2048 + qt * 64 + wid * 16 + (lane >> 2));
    const int qc = lane & 3;
    #pragma unroll
    for (int jd = 0; jd < 16; jd++) {
        atH[row0 * 64 + 4 * jd + qc]       = pack2(oa[jd][0] * i0, oa[jd][1] * i0);
        atH[(row0 + 8) * 64 + 4 * jd + qc] = pack2(oa[jd][2] * i1, oa[jd][3] * i1);
    }
}

// ================= 1-pass GEMM, 128 thr, warp 64x64, BM=BN=128, 2 CTAs/SM ====
template<int EMIT, int EPI>
__global__ __launch_bounds__(128, 2)
void hg1pW(const uint32_t* __restrict__ Ah, const uint32_t* __restrict__ Bh,
           const float* __restrict__ bias, const float* __restrict__ res,
           float* __restrict__ outF, uint32_t* __restrict__ outH,
           int Ka, int Nb, int nc, float alpha)
{
    extern __shared__ char smc[];
    const uint32_t sb = smem_u32(smc);
    const int tid = threadIdx.x, wid = tid >> 5, lane = tid & 31;
    const int wm = wid >> 1, wn = wid & 1;
    const int bx = blockIdx.x, by = blockIdx.y;

    const uint32_t Ka2 = (uint32_t)Ka >> 1, Nb2 = (uint32_t)Nb >> 1;

    // stage 32KB: A@0 16K (128 rows x 128B) | B@16K 16K (64 k-rows x 256B). 3 stages.
    auto load_stage = [&](int st, int c) {
        const uint32_t stb = sb + st * 32768;
        #pragma unroll
        for (int t = 0; t < 8; t++) {
            int id = tid + t * 128;
            int m = id >> 3, ch = id & 7;
            size_t go = (size_t)(by * 128 + m) * Ka2 + (size_t)c * 32 + ch * 4;
            cpasync16(stb + m * 128 + ((ch ^ (m & 7)) << 4), Ah + go);
        }
        #pragma unroll
        for (int t = 0; t < 8; t++) {
            int id = tid + t * 128;
            int k = id >> 4, ch = id & 15;
            size_t go = (size_t)(c * 64 + k) * Nb2 + (size_t)bx * 64 + ch * 4;
            cpasync16(stb + 16384 + k * 256 + ((ch ^ (k & 15)) << 4), Bh + go);
        }
    };

    float acc[4][8][4];
    #pragma unroll
    for (int i = 0; i < 4; i++)
        #pragma unroll
        for (int j = 0; j < 8; j++)
            #pragma unroll
            for (int r = 0; r < 4; r++) acc[i][j][r] = 0.f;

    load_stage(0, 0); CP_COMMIT();
    if (nc > 1) load_stage(1, 1);
    CP_COMMIT();

    const int q = lane >> 3, l7 = lane & 7;

    for (int c = 0; c < nc; ++c) {
        CP_WAIT1();
        __syncthreads();
        if (c + 2 < nc) load_stage((c + 2) % 3, c + 2);
        CP_COMMIT();

        const uint32_t stb = sb + (c % 3) * 32768;
        #pragma unroll
        for (int ks = 0; ks < 4; ks++) {
            uint32_t aH[4][4];
            #pragma unroll
            for (int i = 0; i < 4; i++) {
                int m = wm * 64 + i * 16 + ((q & 1) << 3) + l7;
                int ch = 2 * ks + (q >> 1);
                ldm_x4(aH[i], stb + m * 128 + ((ch ^ (m & 7)) << 4));
            }
            #pragma unroll
            for (int g = 0; g < 4; g++) {
                uint32_t bH4[4];
                int k = ks * 16 + ((q & 1) << 3) + l7;
                int ch = wn * 8 + g * 2 + (q >> 1);
                ldm_x4_t(bH4, stb + 16384 + k * 256 + ((ch ^ (k & 15)) << 4));
                #pragma unroll
                for (int i = 0; i < 4; i++) {
                    mma16816(acc[i][g * 2 + 0], aH[i], &bH4[0]);
                    mma16816(acc[i][g * 2 + 1], aH[i], &bH4[2]);
                }
            }
        }
    }

    __syncthreads();
    float* Cs = (float*)smc;
    #pragma unroll
    for (int i = 0; i < 4; i++)
        #pragma unroll
        for (int j = 0; j < 8; j++) {
            int r0 = wm * 64 + i * 16 + (lane >> 2);
            int c0 = wn * 64 + j * 8 + 2 * (lane & 3);
            *(float2*)(Cs + r0 * 132 + c0)       = make_float2(acc[i][j][0], acc[i][j][1]);
            *(float2*)(Cs + (r0 + 8) * 132 + c0) = make_float2(acc[i][j][2], acc[i][j][3]);
        }
    __syncthreads();

    if (EMIT == EM_F32) {
        #pragma unroll
        for (int i = 0; i < 32; i++) {
            int u = tid + 128 * i;
            int row = u >> 5, c4 = (u & 31) * 4;
            float4 v = *(float4*)(Cs + row * 132 + c4);
            v.x *= alpha; v.y *= alpha; v.z *= alpha; v.w *= alpha;
            int gc = bx * 128 + c4;
            size_t gm = (size_t)by * 128 + row;
            if (EPI & 1) {
                float4 bb = *(const float4*)(bias + gc);
                v.x += bb.x; v.y += bb.y; v.z += bb.z; v.w += bb.w;
            }
            if (EPI & 2) { v.x = gelu1(v.x); v.y = gelu1(v.y); v.z = gelu1(v.z); v.w = gelu1(v.w); }
            if (EPI & 4) {
                float4 rr = *(const float4*)(res + gm * Nb + gc);
                v.x += rr.x; v.y += rr.y; v.z += rr.z; v.w += rr.w;
            }
            *(float4*)(outF + gm * Nb + gc) = v;
        }
    } else { // EM_HF
        #pragma unroll
        for (int i = 0; i < 64; i++) {
            int u = tid + 128 * i;
            int row = u >> 6, np = u & 63;
            float v0 = Cs[row * 132 + 2 * np]     * alpha;
            float v1 = Cs[row * 132 + 2 * np + 1] * alpha;
            int gc = bx * 128 + 2 * np;
            if (EPI & 1) { v0 += __ldg(bias + gc); v1 += __ldg(bias + gc + 1); }
            if (EPI & 2) { v0 = gelu1(v0); v1 = gelu1(v1); }
            size_t gm = (size_t)by * 128 + row;
            outH[gm * (Nb >> 1) + (size_t)bx * 64 + np] = pack2(v0, v1);
        }
    }
}

// ================= 1-pass QKV GEMM, 256 thr, 2 CTAs/SM =======================
__global__ __launch_bounds__(256, 2)
void hgqkv(const uint32_t* __restrict__ Ah, const uint32_t* __restrict__ Bh,
           const float* __restrict__ bias,
           uint32_t* __restrict__ outQ, uint32_t* __restrict__ outKT,
           uint32_t* __restrict__ outV,
           int Ka, int Nb, int nc)
{
    extern __shared__ char smc[];
    const uint32_t sb = smem_u32(smc);
    const int tid = threadIdx.x, wid = tid >> 5, lane = tid & 31;
    const int wm = wid >> 2, wn = wid & 3;
    const int bx = blockIdx.x, by = blockIdx.y;

    const uint32_t Ka2 = (uint32_t)Ka >> 1, Nb2 = (uint32_t)Nb >> 1;

    auto load_stage = [&](int st, int c) {
        const uint32_t stb = sb + st * 32768;
        #pragma unroll
        for (int t = 0; t < 4; t++) {
            int id = tid + t * 256;
            int m = id >> 3, ch = id & 7;
            size_t go = (size_t)(by * 128 + m) * Ka2 + (size_t)c * 32 + ch * 4;
            cpasync16(stb + m * 128 + ((ch ^ (m & 7)) << 4), Ah + go);
        }
        #pragma unroll
        for (int t = 0; t < 4; t++) {
            int id = tid + t * 256;
            int k = id >> 4, ch = id & 15;
            size_t go = (size_t)(c * 64 + k) * Nb2 + (size_t)bx * 64 + ch * 4;
            cpasync16(stb + 16384 + k * 256 + ((ch ^ (k & 15)) << 4), Bh + go);
        }
    };

    float acc[4][4][4];
    #pragma unroll
    for (int i = 0; i < 4; i++)
        #pragma unroll
        for (int j = 0; j < 4; j++)
            #pragma unroll
            for (int r = 0; r < 4; r++) acc[i][j][r] = 0.f;

    load_stage(0, 0); CP_COMMIT();
    load_stage(1, 1); CP_COMMIT();

    const int q = lane >> 3, l7 = lane & 7;

    for (int c = 0; c < nc; ++c) {
        CP_WAIT1();
        __syncthreads();
        if (c + 2 < nc) load_stage((c + 2) % 3, c + 2);
        CP_COMMIT();

        const uint32_t stb = sb + (c % 3) * 32768;
        #pragma unroll
        for (int ks = 0; ks < 4; ks++) {
            uint32_t aH[4][4], bH4[2][4];
            #pragma unroll
            for (int i = 0; i < 4; i++) {
                int m = wm * 64 + i * 16 + ((q & 1) << 3) + l7;
                int ch = 2 * ks + (q >> 1);
                ldm_x4(aH[i], stb + m * 128 + ((ch ^ (m & 7)) << 4));
            }
            #pragma unroll
            for (int g = 0; g < 2; g++) {
                int k = ks * 16 + ((q & 1) << 3) + l7;
                int ch = wn * 4 + g * 2 + (q >> 1);
                ldm_x4_t(bH4[g], stb + 16384 + k * 256 + ((ch ^ (k & 15)) << 4));
            }
            #pragma unroll
            for (int i = 0; i < 4; i++)
                #pragma unroll
                for (int j = 0; j < 4; j++)
                    mma16816(acc[i][j], aH[i], &bH4[j >> 1][(j & 1) * 2]);
        }
    }

    __syncthreads();
    float* Cs = (float*)smc;
    #pragma unroll
    for (int i = 0; i < 4; i++)
        #pragma unroll
        for (int j = 0; j < 4; j++) {
            int r0 = wm * 64 + i * 16 + (lane >> 2);
            int c0 = wn * 32 + j * 8 + 2 * (lane & 3);
            *(float2*)(Cs + r0 * 132 + c0)       = make_float2(acc[i][j][0], acc[i][j][1]);
            *(float2*)(Cs + (r0 + 8) * 132 + c0) = make_float2(acc[i][j][2], acc[i][j][3]);
        }
    __syncthreads();

    if (bx == 1) {            // kT transposed emit
        const int b = by >> 4;
        const int s0p = (by & 15) * 64;
        #pragma unroll
        for (int i = 0; i < 32; i++) {
            int u = tid + 256 * i;
            int d = u >> 6, sp = u & 63;
            float bb = __ldg(bias + 128 + d);
            float v0 = Cs[(2 * sp) * 132 + d]     + bb;
            float v1 = Cs[(2 * sp + 1) * 132 + d] + bb;
            outKT[(size_t)b * (DKV * SEQ / 2) + (size_t)d * (SEQ / 2) + s0p + sp] = pack2(v0, v1);
        }
    } else {
        uint32_t* oh = (bx == 0) ? outQ : outV;
        const int boff = (bx == 0) ? 0 : 256;
        #pragma unroll
        for (int i = 0; i < 32; i++) {
            int u = tid + 256 * i;
            int row = u >> 6, np = u & 63;
            float v0 = Cs[row * 132 + 2 * np]     + __ldg(bias + boff + 2 * np);
            float v1 = Cs[row * 132 + 2 * np + 1] + __ldg(bias + boff + 2 * np + 1);
            oh[((size_t)by * 128 + row) * 64 + np] = pack2(v0, v1);
        }
    }
}

// ---------------- launch sequence -------------------------------------------
extern "C" void kernel_launch(void* const* d_in, const int* in_sizes, int n_in,
                              void* d_out, int out_size)
{
    const float* x     = (const float*)d_in[0];
    const float* ln1_g = (const float*)d_in[1];
    const float* ln1_b = (const float*)d_in[2];
    const float* Wq    = (const float*)d_in[3];
    const float* bq    = (const float*)d_in[4];
    const float* Wk    = (const float*)d_in[5];
    const float* bk    = (const float*)d_in[6];
    const float* Wv    = (const float*)d_in[7];
    const float* bv    = (const float*)d_in[8];
    const float* Wo    = (const float*)d_in[9];
    const float* bo    = (const float*)d_in[10];
    const float* ln2_g = (const float*)d_in[11];
    const float* ln2_b = (const float*)d_in[12];
    const float* W1    = (const float*)d_in[13];
    const float* b1    = (const float*)d_in[14];
    const float* W2    = (const float*)d_in[15];
    const float* b2    = (const float*)d_in[16];
    float* out = (float*)d_out;

    float *xnF, *yF, *bqkv;
    uint32_t *xnH,*hH,*qH,*ktH,*vH,*atH,*acH;
    uint32_t *wqkvH,*woH,*w1H,*w2H;
    cudaGetSymbolAddress((void**)&xnF, g_xnF);
    cudaGetSymbolAddress((void**)&yF,  g_yF);  cudaGetSymbolAddress((void**)&bqkv, g_bqkv);
    cudaGetSymbolAddress((void**)&xnH, g_xnH);
    cudaGetSymbolAddress((void**)&hH,  g_hH);
    cudaGetSymbolAddress((void**)&qH,  g_qH);
    cudaGetSymbolAddress((void**)&ktH, g_ktH);
    cudaGetSymbolAddress((void**)&vH,  g_vH);
    cudaGetSymbolAddress((void**)&atH, g_atH);
    cudaGetSymbolAddress((void**)&acH, g_acH);
    cudaGetSymbolAddress((void**)&wqkvH, g_wqkvH);
    cudaGetSymbolAddress((void**)&woH, g_woH);
    cudaGetSymbolAddress((void**)&w1H, g_w1H);
    cudaGetSymbolAddress((void**)&w2H, g_w2H);

    const int SM_1P = 3 * 32768;            // 96 KB
    const int SM_FL = 16384 + 2 * 32768;    // 80 KB
    cudaFuncSetAttribute(flash_attn,       cudaFuncAttributeMaxDynamicSharedMemorySize, SM_FL);
    cudaFuncSetAttribute(hgqkv,            cudaFuncAttributeMaxDynamicSharedMemorySize, SM_1P);
    cudaFuncSetAttribute(hg1pW<EM_F32,5>,  cudaFuncAttributeMaxDynamicSharedMemorySize, SM_1P);
    cudaFuncSetAttribute(hg1pW<EM_HF, 3>,  cudaFuncAttributeMaxDynamicSharedMemorySize, SM_1P);

    const float scl2 = 0.08838834764831845f * 1.4426950408889634f; // scale*log2(e)

    // ---- weight conversions ----
    {
        WJobs jb;
        jb.src[0] = Wq; jb.H[0] = wqkvH; jb.np[0] = DMODEL*DKV/2; jb.srcP[0] = 64;  jb.dstP[0] = 192; jb.coff[0] = 0;
        jb.src[1] = Wk; jb.H[1] = wqkvH; jb.np[1] = DMODEL*DKV/2; jb.srcP[1] = 64;  jb.dstP[1] = 192; jb.coff[1] = 64;
        jb.src[2] = Wv; jb.H[2] = wqkvH; jb.np[2] = DMODEL*DKV/2; jb.srcP[2] = 64;  jb.dstP[2] = 192; jb.coff[2] = 128;
        jb.src[3] = Wo; jb.H[3] = woH;   jb.np[3] = DKV*DMODEL/2; jb.srcP[3] = 512; jb.dstP[3] = 512; jb.coff[3] = 0;
        jb.src[4] = W1; jb.H[4] = w1H;   jb.np[4] = DMODEL*DFF/2; jb.srcP[4] = 2048;jb.dstP[4] = 2048;jb.coff[4] = 0;
        jb.src[5] = W2; jb.H[5] = w2H;   jb.np[5] = DFF*DMODEL/2; jb.srcP[5] = 512; jb.dstP[5] = 512; jb.coff[5] = 0;
        int acc_ = 0;
        for (int s = 0; s < 6; s++) { jb.blkStart[s] = acc_; acc_ += (jb.np[s] + 255) / 256; }
        jb.blkStart[6] = acc_;
        jb.bq = bq; jb.bk = bk; jb.bv = bv; jb.bqkv = bqkv;
        wconv_all<<<acc_ + 1, 256>>>(jb);
    }

    // 2) ln1 -> xn (f32 + single fp16 pairs)
    ln_frag<true><<<MS, 256>>>(x, ln1_g, ln1_b, xnF, xnH);

    // 3) fused QKV (16384 x 384 x 1024): bx=0 q, 1 kT, 2 v
    hgqkv<<<dim3(3,128,1), 256, SM_1P>>>(xnH, wqkvH, bqkv, qH, ktH, vH, DMODEL, 384, 16);

    // 4) flash attention (64-row tiles, 2 CTA/SM, 256 CTAs) -> att single fp16
    flash_attn<<<dim3(SEQ/64, BATCH), 128, SM_FL>>>(qH, ktH, vH, atH, scl2);

    // 5) y = xn + att@Wo + bo (16384x1024x128) [1-pass]
    hg1pW<EM_F32, 5><<<dim3(8,128,1), 128, SM_1P>>>(atH, woH, bo, xnF,
        yF, nullptr, DKV, DMODEL, 2, 1.f);

    // 6) ln2 -> h single pairs
    ln_frag<false><<<MS, 256>>>(yF, ln2_g, ln2_b, nullptr, hH);

    // 7) act = gelu(h@W1 + b1) (16384x4096x1024) [1-pass]
    hg1pW<EM_HF, 3><<<dim3(32,128,1), 128, SM_1P>>>(hH, w1H, b1, nullptr,
        nullptr, acH, DMODEL, DFF, 16, 1.f);

    // 8) out = y + act@W2 + b2 (16384x1024x4096) [1-pass]
    hg1pW<EM_F32, 5><<<dim3(8,128,1), 128, SM_1P>>>(acH, w2H, b2, yF,
        out, nullptr, DFF, DMODEL, 64, 1.f);
}